// round 1
// baseline (speedup 1.0000x reference)
#include <cuda_runtime.h>
#include <math.h>

#define B_SZ   2
#define HEADS  8
#define S_LEN  2048
#define DM     512
#define HD     64
#define NRPR   513
#define NRPR_PAD 520
#define BH     16   // B_SZ*HEADS

// ---------------- scratch (device globals; no allocation allowed) ----------------
__device__ float g_Qh[BH * S_LEN * HD];        //  8 MB  (b,h,s,d)
__device__ float g_Kh[BH * S_LEN * HD];        //  8 MB
__device__ float g_Vh[BH * S_LEN * HD];        //  8 MB
__device__ float g_P [BH * S_LEN * NRPR_PAD];  // 68 MB  P[bh,i,r] = q_i . Ek_r
__device__ float g_T [BH * S_LEN * NRPR_PAD];  // 68 MB  relative-bucket sums of attn
__device__ float g_SC[BH * S_LEN * HD];        //  8 MB  per-head scores

// =====================================================================
// K1: Q = query@Wq, K = value@Wk, V = value@Wv  -> head layout
// 64x64 tile, BK=16, 256 thr, 4x4 micro
// =====================================================================
__global__ void __launch_bounds__(256) proj_kernel(
    const float* __restrict__ query, const float* __restrict__ value,
    const float* __restrict__ Wq, const float* __restrict__ Wk,
    const float* __restrict__ Wv) {
  const int which = blockIdx.z;
  const float* A = (which == 0) ? query : value;
  const float* W = (which == 0) ? Wq : (which == 1) ? Wk : Wv;
  float* outp    = (which == 0) ? g_Qh : (which == 1) ? g_Kh : g_Vh;

  __shared__ float As[16][68];  // As[k][m]
  __shared__ float Bs[16][68];  // Bs[k][n]
  const int tid = threadIdx.x;
  const int tx = tid & 15, ty = tid >> 4;
  const int m0 = blockIdx.y * 64;
  const int n0 = blockIdx.x * 64;

  float acc[4][4];
#pragma unroll
  for (int i = 0; i < 4; i++)
#pragma unroll
    for (int j = 0; j < 4; j++) acc[i][j] = 0.f;

  const int lr = tid >> 2;         // 0..63  (A row)
  const int lc = (tid & 3) << 2;   // 0..12  (A k chunk)
  const int br = tid >> 4;         // 0..15  (B k row)
  const int bc = (tid & 15) << 2;  // 0..60  (B n chunk)

  for (int k0 = 0; k0 < DM; k0 += 16) {
    float4 va = *(const float4*)(A + (size_t)(m0 + lr) * DM + k0 + lc);
    As[lc + 0][lr] = va.x; As[lc + 1][lr] = va.y;
    As[lc + 2][lr] = va.z; As[lc + 3][lr] = va.w;
    *(float4*)&Bs[br][bc] = *(const float4*)(W + (size_t)(k0 + br) * DM + n0 + bc);
    __syncthreads();
#pragma unroll
    for (int k = 0; k < 16; k++) {
      float4 a = *(float4*)&As[k][ty * 4];
      float4 b = *(float4*)&Bs[k][tx * 4];
      float av[4] = {a.x, a.y, a.z, a.w};
      float bv[4] = {b.x, b.y, b.z, b.w};
#pragma unroll
      for (int i = 0; i < 4; i++)
#pragma unroll
        for (int j = 0; j < 4; j++) acc[i][j] += av[i] * bv[j];
    }
    __syncthreads();
  }
#pragma unroll
  for (int i = 0; i < 4; i++) {
    int row = m0 + ty * 4 + i;
    int b = row >> 11, s = row & (S_LEN - 1);
#pragma unroll
    for (int j = 0; j < 4; j++) {
      int col = n0 + tx * 4 + j;
      int h = col >> 6, d = col & 63;
      outp[(((size_t)(b * HEADS + h)) * S_LEN + s) * HD + d] = acc[i][j];
    }
  }
}

// =====================================================================
// K2: P[bh,i,r] = sum_d Qh[bh,i,d] * Ek[r,d]   (M=2048/bh, N=513, K=64)
// =====================================================================
__global__ void __launch_bounds__(256) p_kernel(const float* __restrict__ Ek) {
  const int bh = blockIdx.z;
  const int i0 = blockIdx.y * 64;
  const int r0 = blockIdx.x * 64;
  __shared__ float As[16][68];  // As[d][i]
  __shared__ float Bs[16][68];  // Bs[d][r]
  const int tid = threadIdx.x;
  const int tx = tid & 15, ty = tid >> 4;
  const float* Qb = g_Qh + (size_t)bh * S_LEN * HD;

  float acc[4][4];
#pragma unroll
  for (int i = 0; i < 4; i++)
#pragma unroll
    for (int j = 0; j < 4; j++) acc[i][j] = 0.f;

  const int lr = tid >> 2;        // 0..63
  const int lc = (tid & 3) << 2;  // 0..12

  for (int k0 = 0; k0 < HD; k0 += 16) {
    float4 va = *(const float4*)(Qb + (size_t)(i0 + lr) * HD + k0 + lc);
    As[lc + 0][lr] = va.x; As[lc + 1][lr] = va.y;
    As[lc + 2][lr] = va.z; As[lc + 3][lr] = va.w;
    float4 vb = make_float4(0.f, 0.f, 0.f, 0.f);
    if (r0 + lr < NRPR)
      vb = *(const float4*)(Ek + (size_t)(r0 + lr) * HD + k0 + lc);
    Bs[lc + 0][lr] = vb.x; Bs[lc + 1][lr] = vb.y;
    Bs[lc + 2][lr] = vb.z; Bs[lc + 3][lr] = vb.w;
    __syncthreads();
#pragma unroll
    for (int k = 0; k < 16; k++) {
      float4 a = *(float4*)&As[k][ty * 4];
      float4 b = *(float4*)&Bs[k][tx * 4];
      float av[4] = {a.x, a.y, a.z, a.w};
      float bv[4] = {b.x, b.y, b.z, b.w};
#pragma unroll
      for (int i = 0; i < 4; i++)
#pragma unroll
        for (int j = 0; j < 4; j++) acc[i][j] += av[i] * bv[j];
    }
    __syncthreads();
  }
#pragma unroll
  for (int i = 0; i < 4; i++) {
    int ii = i0 + ty * 4 + i;
#pragma unroll
    for (int j = 0; j < 4; j++) {
      int rr = r0 + tx * 4 + j;
      if (rr < NRPR)
        g_P[((size_t)bh * S_LEN + ii) * NRPR_PAD + rr] = acc[i][j];
    }
  }
}

// =====================================================================
// K3: alpha[bh,i,j] = (q_i . k_j + P[bh,i,clip(j-i)+256]) / 8
// 128x128 tile, BK=16, 256 thr, 8x8 micro; writes into attn region of d_out
// =====================================================================
__global__ void __launch_bounds__(256) alpha_kernel(float* __restrict__ attn) {
  const int bh = blockIdx.z;
  const int i0 = blockIdx.y * 128;
  const int j0 = blockIdx.x * 128;
  __shared__ float Qs[16][132];  // Qs[k][m]
  __shared__ float Ks[16][132];  // Ks[k][n]
  const int tid = threadIdx.x;
  const int tx = tid & 15, ty = tid >> 4;
  const float* Qb = g_Qh + (size_t)bh * S_LEN * HD;
  const float* Kb = g_Kh + (size_t)bh * S_LEN * HD;

  float acc[8][8];
#pragma unroll
  for (int i = 0; i < 8; i++)
#pragma unroll
    for (int j = 0; j < 8; j++) acc[i][j] = 0.f;

  for (int k0 = 0; k0 < HD; k0 += 16) {
#pragma unroll
    for (int l = 0; l < 2; l++) {
      int idx = tid + 256 * l;        // 0..511
      int row = idx >> 2;             // 0..127
      int c4  = (idx & 3) << 2;       // 0..12
      float4 v = *(const float4*)(Qb + (size_t)(i0 + row) * HD + k0 + c4);
      Qs[c4 + 0][row] = v.x; Qs[c4 + 1][row] = v.y;
      Qs[c4 + 2][row] = v.z; Qs[c4 + 3][row] = v.w;
      float4 w = *(const float4*)(Kb + (size_t)(j0 + row) * HD + k0 + c4);
      Ks[c4 + 0][row] = w.x; Ks[c4 + 1][row] = w.y;
      Ks[c4 + 2][row] = w.z; Ks[c4 + 3][row] = w.w;
    }
    __syncthreads();
#pragma unroll
    for (int k = 0; k < 16; k++) {
      float a[8], b[8];
      *(float4*)&a[0] = *(float4*)&Qs[k][ty * 8];
      *(float4*)&a[4] = *(float4*)&Qs[k][ty * 8 + 4];
      *(float4*)&b[0] = *(float4*)&Ks[k][tx * 8];
      *(float4*)&b[4] = *(float4*)&Ks[k][tx * 8 + 4];
#pragma unroll
      for (int i = 0; i < 8; i++)
#pragma unroll
        for (int j = 0; j < 8; j++) acc[i][j] += a[i] * b[j];
    }
    __syncthreads();
  }
#pragma unroll
  for (int ii = 0; ii < 8; ii++) {
    int i = i0 + ty * 8 + ii;
    const float* Prow = g_P + ((size_t)bh * S_LEN + i) * NRPR_PAD;
    float* orow = attn + ((size_t)bh * S_LEN + i) * S_LEN + j0 + tx * 8;
    float o[8];
#pragma unroll
    for (int jj = 0; jj < 8; jj++) {
      int j = j0 + tx * 8 + jj;
      int rel = j - i;
      rel = rel < -256 ? -256 : (rel > 256 ? 256 : rel);
      o[jj] = (acc[ii][jj] + Prow[rel + 256]) * 0.125f;
    }
    *(float4*)&orow[0] = make_float4(o[0], o[1], o[2], o[3]);
    *(float4*)&orow[4] = make_float4(o[4], o[5], o[6], o[7]);
  }
}

// =====================================================================
// K4: in-place row softmax over attn + build T buckets
// one block per (bh,i) row; row lives in SMEM (8 KB)
// =====================================================================
__global__ void __launch_bounds__(256) softmax_t_kernel(float* __restrict__ attn) {
  const int row = blockIdx.x;          // bh*S + i
  const int i = row & (S_LEN - 1);
  const int tid = threadIdx.x;
  const int lane = tid & 31, warp = tid >> 5;
  __shared__ float buf[S_LEN];
  __shared__ float redA[8], redB[8];
  float* rp = attn + (size_t)row * S_LEN;

  float4 v0 = *(const float4*)(rp + tid * 4);
  float4 v1 = *(const float4*)(rp + 1024 + tid * 4);
  float lmax = fmaxf(fmaxf(fmaxf(v0.x, v0.y), fmaxf(v0.z, v0.w)),
                     fmaxf(fmaxf(v1.x, v1.y), fmaxf(v1.z, v1.w)));
#pragma unroll
  for (int o = 16; o > 0; o >>= 1) lmax = fmaxf(lmax, __shfl_xor_sync(~0u, lmax, o));
  if (lane == 0) redA[warp] = lmax;
  __syncthreads();
  float mx = redA[0];
#pragma unroll
  for (int k = 1; k < 8; k++) mx = fmaxf(mx, redA[k]);

  float e[8];
  e[0] = __expf(v0.x - mx); e[1] = __expf(v0.y - mx);
  e[2] = __expf(v0.z - mx); e[3] = __expf(v0.w - mx);
  e[4] = __expf(v1.x - mx); e[5] = __expf(v1.y - mx);
  e[6] = __expf(v1.z - mx); e[7] = __expf(v1.w - mx);
  float ls = ((e[0] + e[1]) + (e[2] + e[3])) + ((e[4] + e[5]) + (e[6] + e[7]));
#pragma unroll
  for (int o = 16; o > 0; o >>= 1) ls += __shfl_xor_sync(~0u, ls, o);
  if (lane == 0) redB[warp] = ls;
  __syncthreads();
  float tot = redB[0];
#pragma unroll
  for (int k = 1; k < 8; k++) tot += redB[k];
  float inv = 1.0f / tot;

  float4 n0 = make_float4(e[0] * inv, e[1] * inv, e[2] * inv, e[3] * inv);
  float4 n1 = make_float4(e[4] * inv, e[5] * inv, e[6] * inv, e[7] * inv);
  *(float4*)(rp + tid * 4) = n0;
  *(float4*)(rp + 1024 + tid * 4) = n1;
  *(float4*)&buf[tid * 4] = n0;
  *(float4*)&buf[1024 + tid * 4] = n1;
  __syncthreads();

  // middle buckets: r=1..511 maps to single j = i + r - 256
  const size_t tb = (size_t)row * NRPR_PAD;
  for (int r = tid; r < NRPR; r += 256) {
    if (r == 0 || r == NRPR - 1) continue;
    int j = i + r - 256;
    g_T[tb + r] = (j >= 0 && j < S_LEN) ? buf[j] : 0.f;
  }
  // clipped buckets: r=0 sums j<=i-256 ; r=512 sums j>=i+256
  float lo = 0.f, hi = 0.f;
  for (int j = tid; j <= i - 256; j += 256) lo += buf[j];
  for (int j = i + 256 + tid; j < S_LEN; j += 256) hi += buf[j];
#pragma unroll
  for (int o = 16; o > 0; o >>= 1) {
    lo += __shfl_xor_sync(~0u, lo, o);
    hi += __shfl_xor_sync(~0u, hi, o);
  }
  if (lane == 0) { redA[warp] = lo; redB[warp] = hi; }
  __syncthreads();
  if (tid == 0) {
    float los = 0.f, his = 0.f;
#pragma unroll
    for (int k = 0; k < 8; k++) { los += redA[k]; his += redB[k]; }
    g_T[tb] = los;
    g_T[tb + NRPR - 1] = his;
  }
}

// =====================================================================
// K5: scores = attn @ Vh + T @ Ev   (per bh: M=2048, N=64, K=2048+513)
// 128-row tile, BK=32, 256 thr, 8x4 micro
// =====================================================================
__global__ void __launch_bounds__(256) av_kernel(const float* __restrict__ attn,
                                                 const float* __restrict__ Ev) {
  const int bh = blockIdx.y;
  const int i0 = blockIdx.x * 128;
  __shared__ float As[32][132];  // As[k][m]
  __shared__ float Bs[32][68];   // Bs[k][n]
  const int tid = threadIdx.x;
  const int tx = tid & 15, ty = tid >> 4;
  const float* Ab = attn + ((size_t)bh * S_LEN + i0) * S_LEN;
  const float* Vb = g_Vh + (size_t)bh * S_LEN * HD;

  float acc[8][4];
#pragma unroll
  for (int i = 0; i < 8; i++)
#pragma unroll
    for (int j = 0; j < 4; j++) acc[i][j] = 0.f;

  for (int j0 = 0; j0 < S_LEN; j0 += 32) {
#pragma unroll
    for (int l = 0; l < 4; l++) {
      int idx = tid + 256 * l;        // 0..1023
      int r = idx >> 3;               // 0..127
      int c4 = (idx & 7) << 2;        // 0..28
      float4 v = *(const float4*)(Ab + (size_t)r * S_LEN + j0 + c4);
      As[c4 + 0][r] = v.x; As[c4 + 1][r] = v.y;
      As[c4 + 2][r] = v.z; As[c4 + 3][r] = v.w;
    }
#pragma unroll
    for (int l = 0; l < 2; l++) {
      int idx = tid + 256 * l;        // 0..511
      int r = idx >> 4;               // 0..31
      int c4 = (idx & 15) << 2;       // 0..60
      *(float4*)&Bs[r][c4] = *(const float4*)(Vb + (size_t)(j0 + r) * HD + c4);
    }
    __syncthreads();
#pragma unroll
    for (int k = 0; k < 32; k++) {
      float a[8], b[4];
      *(float4*)&a[0] = *(float4*)&As[k][ty * 8];
      *(float4*)&a[4] = *(float4*)&As[k][ty * 8 + 4];
      *(float4*)&b[0] = *(float4*)&Bs[k][tx * 4];
#pragma unroll
      for (int i = 0; i < 8; i++)
#pragma unroll
        for (int j = 0; j < 4; j++) acc[i][j] += a[i] * b[j];
    }
    __syncthreads();
  }

  // T @ Ev over r = 0..511 (full 32-wide tiles); r=512 handled in epilogue
  for (int r0 = 0; r0 < 512; r0 += 32) {
#pragma unroll
    for (int l = 0; l < 4; l++) {
      int idx = tid + 256 * l;
      int r = idx >> 3;
      int c4 = (idx & 7) << 2;
      float4 v = *(const float4*)(g_T + ((size_t)bh * S_LEN + i0 + r) * NRPR_PAD + r0 + c4);
      As[c4 + 0][r] = v.x; As[c4 + 1][r] = v.y;
      As[c4 + 2][r] = v.z; As[c4 + 3][r] = v.w;
    }
#pragma unroll
    for (int l = 0; l < 2; l++) {
      int idx = tid + 256 * l;
      int r = idx >> 4;
      int c4 = (idx & 15) << 2;
      *(float4*)&Bs[r][c4] = *(const float4*)(Ev + (size_t)(r0 + r) * HD + c4);
    }
    __syncthreads();
#pragma unroll
    for (int k = 0; k < 32; k++) {
      float a[8], b[4];
      *(float4*)&a[0] = *(float4*)&As[k][ty * 8];
      *(float4*)&a[4] = *(float4*)&As[k][ty * 8 + 4];
      *(float4*)&b[0] = *(float4*)&Bs[k][tx * 4];
#pragma unroll
      for (int i = 0; i < 8; i++)
#pragma unroll
        for (int j = 0; j < 4; j++) acc[i][j] += a[i] * b[j];
    }
    __syncthreads();
  }

#pragma unroll
  for (int ii = 0; ii < 8; ii++) {
    int i = i0 + ty * 8 + ii;
    float t512 = g_T[((size_t)bh * S_LEN + i) * NRPR_PAD + (NRPR - 1)];
    float o[4];
#pragma unroll
    for (int jj = 0; jj < 4; jj++)
      o[jj] = acc[ii][jj] + t512 * Ev[(size_t)(NRPR - 1) * HD + tx * 4 + jj];
    *(float4*)(g_SC + ((size_t)bh * S_LEN + i) * HD + tx * 4) =
        make_float4(o[0], o[1], o[2], o[3]);
  }
}

// =====================================================================
// K6: out = concat(scores) @ Wo + bo   (M=4096, N=512, K=512)
// =====================================================================
__global__ void __launch_bounds__(256) out_kernel(const float* __restrict__ Wo,
                                                  const float* __restrict__ bo,
                                                  float* __restrict__ out) {
  __shared__ float As[16][68];
  __shared__ float Bs[16][68];
  const int tid = threadIdx.x;
  const int tx = tid & 15, ty = tid >> 4;
  const int m0 = blockIdx.y * 64;
  const int n0 = blockIdx.x * 64;

  float acc[4][4];
#pragma unroll
  for (int i = 0; i < 4; i++)
#pragma unroll
    for (int j = 0; j < 4; j++) acc[i][j] = 0.f;

  const int lr = tid >> 2;
  const int lc = (tid & 3) << 2;
  const int br = tid >> 4;
  const int bc = (tid & 15) << 2;
  const int bs = m0 + lr;
  const int b = bs >> 11, s = bs & (S_LEN - 1);

  for (int k0 = 0; k0 < DM; k0 += 16) {
    int c = k0 + lc;  // within one head (k0 mult of 16)
    const float* src = g_SC + (((size_t)(b * HEADS + (c >> 6))) * S_LEN + s) * HD + (c & 63);
    float4 va = *(const float4*)src;
    As[lc + 0][lr] = va.x; As[lc + 1][lr] = va.y;
    As[lc + 2][lr] = va.z; As[lc + 3][lr] = va.w;
    *(float4*)&Bs[br][bc] = *(const float4*)(Wo + (size_t)(k0 + br) * DM + n0 + bc);
    __syncthreads();
#pragma unroll
    for (int k = 0; k < 16; k++) {
      float4 a = *(float4*)&As[k][ty * 4];
      float4 bb = *(float4*)&Bs[k][tx * 4];
      float av[4] = {a.x, a.y, a.z, a.w};
      float bv[4] = {bb.x, bb.y, bb.z, bb.w};
#pragma unroll
      for (int i = 0; i < 4; i++)
#pragma unroll
        for (int j = 0; j < 4; j++) acc[i][j] += av[i] * bv[j];
    }
    __syncthreads();
  }
#pragma unroll
  for (int i = 0; i < 4; i++) {
    int row = m0 + ty * 4 + i;
#pragma unroll
    for (int j = 0; j < 4; j++) {
      int col = n0 + tx * 4 + j;
      out[(size_t)row * DM + col] = acc[i][j] + bo[col];
    }
  }
}

// =====================================================================
extern "C" void kernel_launch(void* const* d_in, const int* in_sizes, int n_in,
                              void* d_out, int out_size) {
  const float* query = (const float*)d_in[0];
  const float* value = (const float*)d_in[1];
  const float* Wq    = (const float*)d_in[2];
  const float* Wk    = (const float*)d_in[3];
  const float* Wv    = (const float*)d_in[4];
  const float* Wo    = (const float*)d_in[5];
  const float* bo    = (const float*)d_in[6];
  const float* Ek    = (const float*)d_in[7];
  const float* Ev    = (const float*)d_in[8];

  float* out  = (float*)d_out;                       // (B,S,DM)
  float* attn = out + (size_t)B_SZ * S_LEN * DM;     // (B,H,S,S)

  proj_kernel     <<<dim3(8, 64, 3),  256>>>(query, value, Wq, Wk, Wv);
  p_kernel        <<<dim3(9, 32, BH), 256>>>(Ek);
  alpha_kernel    <<<dim3(16, 16, BH),256>>>(attn);
  softmax_t_kernel<<<BH * S_LEN,      256>>>(attn);
  av_kernel       <<<dim3(16, BH),    256>>>(attn, Ev);
  out_kernel      <<<dim3(8, 64),     256>>>(Wo, bo, out);
}